// round 9
// baseline (speedup 1.0000x reference)
#include <cuda_runtime.h>

#define B_ 4
#define S_ 2048
#define E_ 1024
#define A_ 128
#define M_ (B_*S_)   // 8192

typedef unsigned long long u64;

// ---- packed fp32x2 helpers (SASS FFMA2 path) ----
__device__ __forceinline__ void ffma2(u64& d, u64 a, u64 b) {
    asm("fma.rn.f32x2 %0, %1, %2, %0;" : "+l"(d) : "l"(a), "l"(b));
}
__device__ __forceinline__ void fmul2(u64& d, u64 a) {
    asm("mul.rn.f32x2 %0, %0, %1;" : "+l"(d) : "l"(a));
}
__device__ __forceinline__ u64 pack2(float lo, float hi) {
    u64 r;
    asm("mov.b64 %0, {%1, %2};" : "=l"(r)
        : "r"(__float_as_uint(lo)), "r"(__float_as_uint(hi)));
    return r;
}
__device__ __forceinline__ void unpack2(u64 p, float& lo, float& hi) {
    unsigned ulo, uhi;
    asm("mov.b64 {%0, %1}, %2;" : "=r"(ulo), "=r"(uhi) : "l"(p));
    lo = __uint_as_float(ulo); hi = __uint_as_float(uhi);
}
__device__ __forceinline__ u64 swap2(u64 p) {
    float lo, hi; unpack2(p, lo, hi); return pack2(hi, lo);
}

// scratch (device globals: no allocation allowed)
__device__ float g_q [M_*A_];        // [b][s][a], pre-scaled by 1/sqrt(A)
__device__ float g_kt[B_*A_*S_];     // [b][a][s]  (K transposed)
__device__ float g_v [M_*A_];        // [b][s][a]

// ---------------------------------------------------------------------------
// Projection with FFMA2. grid (128, 3), block 256.
// __launch_bounds__(256,2): cap regs at 128 -> 2 CTAs/SM so LDS latency of
// one CTA is covered by the other (round-8 finding: LDS+FMA serialize at occ 1).
// ---------------------------------------------------------------------------
#define KT 32
#define XTP 68   // xs_t pitch (floats)

__global__ __launch_bounds__(256, 2) void proj_kernel(
    const float* __restrict__ x,
    const float* __restrict__ Wk,
    const float* __restrict__ Wq,
    const float* __restrict__ Wv)
{
    const int which = blockIdx.y;               // 0=K, 1=Q, 2=V
    const float* __restrict__ W = (which == 0) ? Wk : ((which == 1) ? Wq : Wv);
    const int m0  = blockIdx.x * 64;
    const int tid = threadIdx.x;
    const int c   = tid & 31;
    const int r   = tid >> 5;

    __shared__ float xs_t[KT * XTP];     // [kk][row]
    __shared__ float ws[128 * 33];       // [n][kk]

    u64 acc[4][4];
#pragma unroll
    for (int p = 0; p < 4; p++)
#pragma unroll
        for (int j = 0; j < 4; j++) acc[p][j] = 0ull;

    const int xrow = tid >> 2;            // 0..63
    const int xcb  = (tid & 3) * 8;       // 0,8,16,24
    const int wrow = tid >> 1;            // 0..127
    const int wcb  = (tid & 1) * 16;      // 0,16

    for (int kt = 0; kt < E_; kt += KT) {
        float4 xa = *(const float4*)&x[(m0 + xrow) * E_ + kt + xcb];
        float4 xb = *(const float4*)&x[(m0 + xrow) * E_ + kt + xcb + 4];
        float4 w0 = *(const float4*)&W[wrow * E_ + kt + wcb];
        float4 w1 = *(const float4*)&W[wrow * E_ + kt + wcb + 4];
        float4 w2 = *(const float4*)&W[wrow * E_ + kt + wcb + 8];
        float4 w3 = *(const float4*)&W[wrow * E_ + kt + wcb + 12];

        __syncthreads();
        {
            float xv[8] = {xa.x, xa.y, xa.z, xa.w, xb.x, xb.y, xb.z, xb.w};
#pragma unroll
            for (int u = 0; u < 8; u++)
                xs_t[(xcb + u) * XTP + xrow] = xv[u];
            float* pw = &ws[wrow * 33 + wcb];
            pw[0]=w0.x; pw[1]=w0.y; pw[2]=w0.z; pw[3]=w0.w;
            pw[4]=w1.x; pw[5]=w1.y; pw[6]=w1.z; pw[7]=w1.w;
            pw[8]=w2.x; pw[9]=w2.y; pw[10]=w2.z; pw[11]=w2.w;
            pw[12]=w3.x; pw[13]=w3.y; pw[14]=w3.z; pw[15]=w3.w;
        }
        __syncthreads();

#pragma unroll 4
        for (int kk = 0; kk < KT; kk++) {
            const float* xt = &xs_t[kk * XTP + r * 8];
            ulonglong2 av0 = *(const ulonglong2*)xt;
            ulonglong2 av1 = *(const ulonglong2*)(xt + 4);
            u64 B0 = pack2(ws[(c      ) * 33 + kk], ws[(c      ) * 33 + kk]);
            u64 B1 = pack2(ws[(c + 32 ) * 33 + kk], ws[(c + 32 ) * 33 + kk]);
            u64 B2 = pack2(ws[(c + 64 ) * 33 + kk], ws[(c + 64 ) * 33 + kk]);
            u64 B3 = pack2(ws[(c + 96 ) * 33 + kk], ws[(c + 96 ) * 33 + kk]);
            ffma2(acc[0][0], av0.x, B0); ffma2(acc[0][1], av0.x, B1);
            ffma2(acc[0][2], av0.x, B2); ffma2(acc[0][3], av0.x, B3);
            ffma2(acc[1][0], av0.y, B0); ffma2(acc[1][1], av0.y, B1);
            ffma2(acc[1][2], av0.y, B2); ffma2(acc[1][3], av0.y, B3);
            ffma2(acc[2][0], av1.x, B0); ffma2(acc[2][1], av1.x, B1);
            ffma2(acc[2][2], av1.x, B2); ffma2(acc[2][3], av1.x, B3);
            ffma2(acc[3][0], av1.y, B0); ffma2(acc[3][1], av1.y, B1);
            ffma2(acc[3][2], av1.y, B2); ffma2(acc[3][3], av1.y, B3);
        }
    }

    const float qscale = 0.08838834764831843f;  // 1/sqrt(128)
#pragma unroll
    for (int p = 0; p < 4; p++) {
#pragma unroll
        for (int j = 0; j < 4; j++) {
            float vA, vB; unpack2(acc[p][j], vA, vB);
            const int n = c + 32 * j;
#pragma unroll
            for (int h = 0; h < 2; h++) {
                const int m = m0 + r * 8 + 2 * p + h;
                float v = h ? vB : vA;
                if (which == 1) {
                    g_q[m * A_ + n] = v * qscale;
                } else if (which == 2) {
                    g_v[m * A_ + n] = v;
                } else {
                    const int bb = m >> 11;
                    const int s  = m & (S_ - 1);
                    g_kt[(bb * A_ + n) * S_ + s] = v;
                }
            }
        }
    }
}

// ---------------------------------------------------------------------------
// Flash attention (causal), fp32 via FFMA2, 2 CTAs/SM.
// BM=32, BN=64, block 128 (4 warps). smem = 96 KB -> 2 resident CTAs per SM
// (round-8 finding: at 1 CTA/SM LDS latency serializes the crossbar and FMA
// phases; a second independent CTA overlaps them).
// Warp w owns rows w*8..w*8+7 and ALL 64 keys of the tile:
//   lane l: rh=l>>4 -> rows rowbase=w*8+rh*4 .. +3
//   QK cols: keys cl4=(l&15)*4 .. +3       (4r x 4c micro-tile)
//   PV cols: dims cpv=(l&15)*8 .. +7       (4r x 8c micro-tile)
// Softmax: pure 16-lane shfl (warp spans all keys) + __syncwarp to PV.
// ---------------------------------------------------------------------------
#define BM 32
#define BN 64
#define KP 68    // k_s pitch
#define VP 132   // v_s pitch
#define TP 36    // q_t/p_t pitch

// q_t[128][36] + k_s[128][68] + v_s[64][132] + p_t[64][36]
#define ATTN_SMEM ((128*36 + 128*68 + 64*132 + 64*36) * 4)

__global__ __launch_bounds__(128, 2) void attn_kernel(float* __restrict__ out)
{
    extern __shared__ float sm[];
    float* q_t = sm;                    // [128][TP]  q_t[d][row]
    float* k_s = q_t + 128 * TP;        // [128][KP]  k_s[d][key]
    float* v_s = k_s + 128 * KP;        // [64][VP]   v_s[key][d]
    float* p_t = v_s + 64  * VP;        // [64][TP]   p_t[key][row]

    const int qt  = 63 - blockIdx.x;    // longest CTAs first
    const int b   = blockIdx.y;
    const int q0  = qt * BM;
    const int tid = threadIdx.x;
    const int w   = tid >> 5;
    const int l   = tid & 31;

    const int rh      = l >> 4;              // 0..1
    const int rowbase = w * 8 + rh * 4;      // rows rowbase..rowbase+3
    const int cl4     = (l & 15) * 4;        // QK: keys cl4..cl4+3
    const int cpv     = (l & 15) * 8;        // PV: dims cpv..cpv+7

    // stage Q transposed: q_t[d][row]  (32 rows x 128 d)
    {
        const int row = tid >> 2;              // 0..31
        const int cb  = (tid & 3) * 32;        // 0,32,64,96
        const float* gq = &g_q[(b * S_ + q0 + row) * A_ + cb];
#pragma unroll
        for (int u = 0; u < 8; u++) {
            float4 qv = *(const float4*)(gq + u * 4);
            q_t[(cb + u * 4 + 0) * TP + row] = qv.x;
            q_t[(cb + u * 4 + 1) * TP + row] = qv.y;
            q_t[(cb + u * 4 + 2) * TP + row] = qv.z;
            q_t[(cb + u * 4 + 3) * TP + row] = qv.w;
        }
    }

    float m_i[4], l_i[4];
    u64 o2[2][4][2];   // [rowpair][colpair][aligned/swapped]
#pragma unroll
    for (int i = 0; i < 4; i++) { m_i[i] = -1e30f; l_i[i] = 0.f; }
#pragma unroll
    for (int rp = 0; rp < 2; rp++)
#pragma unroll
        for (int cp = 0; cp < 4; cp++) { o2[rp][cp][0] = 0ull; o2[rp][cp][1] = 0ull; }

    const int ntiles = (qt >> 1) + 1;

    for (int t = 0; t < ntiles; t++) {
        const int kb = t * BN;

        __syncthreads();   // q_t ready (t=0) / all warps done with prev k_s,v_s
        {
            // K tile: k_s[d][key], d = tid, 64 keys
            const float* gk = &g_kt[(b * A_ + tid) * S_ + kb];
            float* dk = &k_s[tid * KP];
#pragma unroll
            for (int u = 0; u < 16; u++)
                *(float4*)(dk + u * 4) = *(const float4*)(gk + u * 4);
            // V tile: v_s[key][d], key = tid>>1, half of d per thread
            const int vrow = tid >> 1;
            const int vcb  = (tid & 1) * 64;
            const float* gv = &g_v[(b * S_ + kb + vrow) * A_ + vcb];
            float* dv = &v_s[vrow * VP + vcb];
#pragma unroll
            for (int u = 0; u < 16; u++)
                *(float4*)(dv + u * 4) = *(const float4*)(gv + u * 4);
        }
        __syncthreads();

        // ---- S = Q K^T : swap-trick 2x2 blocks over 4r x 4c ----
        u64 s2[2][2][2];
#pragma unroll
        for (int rp = 0; rp < 2; rp++)
#pragma unroll
            for (int cp = 0; cp < 2; cp++) { s2[rp][cp][0] = 0ull; s2[rp][cp][1] = 0ull; }

#pragma unroll 4
        for (int kk = 0; kk < 128; kk++) {
            ulonglong2 aq = *(const ulonglong2*)&q_t[kk * TP + rowbase];
            ulonglong2 bk = *(const ulonglong2*)&k_s[kk * KP + cl4];
            u64 b0s = swap2(bk.x);
            u64 b1s = swap2(bk.y);
            ffma2(s2[0][0][0], aq.x, bk.x);
            ffma2(s2[0][0][1], aq.x, b0s);
            ffma2(s2[0][1][0], aq.x, bk.y);
            ffma2(s2[0][1][1], aq.x, b1s);
            ffma2(s2[1][0][0], aq.y, bk.x);
            ffma2(s2[1][0][1], aq.y, b0s);
            ffma2(s2[1][1][0], aq.y, bk.y);
            ffma2(s2[1][1][1], aq.y, b1s);
        }

        // unscramble -> s[row][col]
        float s[4][4];
#pragma unroll
        for (int rp = 0; rp < 2; rp++)
#pragma unroll
            for (int cp = 0; cp < 2; cp++) {
                float a0, a1, b0, b1;
                unpack2(s2[rp][cp][0], a0, a1);
                unpack2(s2[rp][cp][1], b0, b1);
                s[2*rp  ][2*cp  ] = a0;
                s[2*rp+1][2*cp+1] = a1;
                s[2*rp  ][2*cp+1] = b0;
                s[2*rp+1][2*cp  ] = b1;
            }

        // causal mask (only the diagonal tile)
        if (t == ntiles - 1) {
#pragma unroll
            for (int i = 0; i < 4; i++) {
                const int qg = q0 + rowbase + i;
#pragma unroll
                for (int j = 0; j < 4; j++)
                    if (kb + cl4 + j > qg) s[i][j] = -1e30f;
            }
        }

        // ---- online softmax: warp spans all 64 keys -> 16-lane shfl only ----
        float al[4], p[4][4];
#pragma unroll
        for (int i = 0; i < 4; i++) {
            float mx = fmaxf(fmaxf(s[i][0], s[i][1]), fmaxf(s[i][2], s[i][3]));
#pragma unroll
            for (int off = 8; off > 0; off >>= 1)
                mx = fmaxf(mx, __shfl_xor_sync(0xffffffffu, mx, off));
            const float mnew = fmaxf(m_i[i], mx);
            al[i] = __expf(m_i[i] - mnew);
            p[i][0] = __expf(s[i][0] - mnew);
            p[i][1] = __expf(s[i][1] - mnew);
            p[i][2] = __expf(s[i][2] - mnew);
            p[i][3] = __expf(s[i][3] - mnew);
            float ss = (p[i][0] + p[i][1]) + (p[i][2] + p[i][3]);
#pragma unroll
            for (int off = 8; off > 0; off >>= 1)
                ss += __shfl_xor_sync(0xffffffffu, ss, off);
            l_i[i] = l_i[i] * al[i] + ss;
            m_i[i] = mnew;
        }
        // write P transposed: p_t[key][row]
#pragma unroll
        for (int j = 0; j < 4; j++)
            *(float4*)&p_t[(cl4 + j) * TP + rowbase] =
                make_float4(p[0][j], p[1][j], p[2][j], p[3][j]);
        // rescale O
        {
            u64 a01 = pack2(al[0], al[1]);
            u64 a23 = pack2(al[2], al[3]);
#pragma unroll
            for (int cp = 0; cp < 4; cp++) {
                fmul2(o2[0][cp][0], a01); fmul2(o2[0][cp][1], a01);
                fmul2(o2[1][cp][0], a23); fmul2(o2[1][cp][1], a23);
            }
        }
        __syncwarp();   // p_t rows for this warp written by this warp only

        // ---- O += P V : 4r x 8c micro-tile (1.5 B/MAC) ----
#pragma unroll 4
        for (int kk = 0; kk < 64; kk++) {
            ulonglong2 ap  = *(const ulonglong2*)&p_t[kk * TP + rowbase];
            ulonglong2 bv0 = *(const ulonglong2*)&v_s[kk * VP + cpv];
            ulonglong2 bv1 = *(const ulonglong2*)&v_s[kk * VP + cpv + 4];
            u64 c0 = bv0.x, c1 = bv0.y, c2 = bv1.x, c3 = bv1.y;
            u64 c0s = swap2(c0), c1s = swap2(c1), c2s = swap2(c2), c3s = swap2(c3);
            ffma2(o2[0][0][0], ap.x, c0); ffma2(o2[0][0][1], ap.x, c0s);
            ffma2(o2[0][1][0], ap.x, c1); ffma2(o2[0][1][1], ap.x, c1s);
            ffma2(o2[0][2][0], ap.x, c2); ffma2(o2[0][2][1], ap.x, c2s);
            ffma2(o2[0][3][0], ap.x, c3); ffma2(o2[0][3][1], ap.x, c3s);
            ffma2(o2[1][0][0], ap.y, c0); ffma2(o2[1][0][1], ap.y, c0s);
            ffma2(o2[1][1][0], ap.y, c1); ffma2(o2[1][1][1], ap.y, c1s);
            ffma2(o2[1][2][0], ap.y, c2); ffma2(o2[1][2][1], ap.y, c2s);
            ffma2(o2[1][3][0], ap.y, c3); ffma2(o2[1][3][1], ap.y, c3s);
        }
    }

    // ---- epilogue: unscramble, normalize, store 4 rows x 8 cols ----
    float o[4][8];
#pragma unroll
    for (int rp = 0; rp < 2; rp++)
#pragma unroll
        for (int cp = 0; cp < 4; cp++) {
            float a0, a1, b0, b1;
            unpack2(o2[rp][cp][0], a0, a1);
            unpack2(o2[rp][cp][1], b0, b1);
            o[2*rp  ][2*cp  ] = a0;
            o[2*rp+1][2*cp+1] = a1;
            o[2*rp  ][2*cp+1] = b0;
            o[2*rp+1][2*cp  ] = b1;
        }
#pragma unroll
    for (int i = 0; i < 4; i++) {
        const float inv = 1.f / l_i[i];
        float* po = &out[(b * S_ + q0 + rowbase + i) * A_ + cpv];
        float4 r0 = make_float4(o[i][0]*inv, o[i][1]*inv, o[i][2]*inv, o[i][3]*inv);
        float4 r1 = make_float4(o[i][4]*inv, o[i][5]*inv, o[i][6]*inv, o[i][7]*inv);
        *(float4*)(po    ) = r0;
        *(float4*)(po + 4) = r1;
    }
}

// ---------------------------------------------------------------------------
extern "C" void kernel_launch(void* const* d_in, const int* in_sizes, int n_in,
                              void* d_out, int out_size)
{
    const float* x  = (const float*)d_in[0];   // embedded [4,2048,1024]
    const float* Wk = (const float*)d_in[1];   // [128,1024]
    const float* Wq = (const float*)d_in[2];
    const float* Wv = (const float*)d_in[3];
    float* out = (float*)d_out;                // [4,2048,128] fp32

    cudaFuncSetAttribute(attn_kernel,
                         cudaFuncAttributeMaxDynamicSharedMemorySize,
                         ATTN_SMEM);

    proj_kernel<<<dim3(M_ / 64, 3), 256>>>(x, Wk, Wq, Wv);
    attn_kernel<<<dim3(64, B_), 128, ATTN_SMEM>>>(out);
}

// round 11
// speedup vs baseline: 1.3000x; 1.3000x over previous
#include <cuda_runtime.h>
#include <cuda_bf16.h>
#include <cstdint>

#define B_ 4
#define S_ 2048
#define E_ 1024
#define A_ 128
#define M_ (B_*S_)   // 8192

typedef unsigned long long u64;

// ---- packed fp32x2 helpers (attn kernel, proven R8 path) ----
__device__ __forceinline__ void ffma2(u64& d, u64 a, u64 b) {
    asm("fma.rn.f32x2 %0, %1, %2, %0;" : "+l"(d) : "l"(a), "l"(b));
}
__device__ __forceinline__ void fmul2(u64& d, u64 a) {
    asm("mul.rn.f32x2 %0, %0, %1;" : "+l"(d) : "l"(a));
}
__device__ __forceinline__ u64 pack2(float lo, float hi) {
    u64 r;
    asm("mov.b64 %0, {%1, %2};" : "=l"(r)
        : "r"(__float_as_uint(lo)), "r"(__float_as_uint(hi)));
    return r;
}
__device__ __forceinline__ void unpack2(u64 p, float& lo, float& hi) {
    unsigned ulo, uhi;
    asm("mov.b64 {%0, %1}, %2;" : "=r"(ulo), "=r"(uhi) : "l"(p));
    lo = __uint_as_float(ulo); hi = __uint_as_float(uhi);
}
__device__ __forceinline__ u64 swap2(u64 p) {
    float lo, hi; unpack2(p, lo, hi); return pack2(hi, lo);
}

// ---- mma.sync bf16 (base ISA, compiles for compute_103) ----
__device__ __forceinline__ void mma16816(float* d, const unsigned* a, const unsigned* b) {
    asm volatile(
        "mma.sync.aligned.m16n8k16.row.col.f32.bf16.bf16.f32 "
        "{%0,%1,%2,%3}, {%4,%5,%6,%7}, {%8,%9}, {%0,%1,%2,%3};"
        : "+f"(d[0]), "+f"(d[1]), "+f"(d[2]), "+f"(d[3])
        : "r"(a[0]), "r"(a[1]), "r"(a[2]), "r"(a[3]), "r"(b[0]), "r"(b[1]));
}

__device__ __forceinline__ unsigned pack_bf16_hi(float a, float b) {
    __nv_bfloat162 h = __floats2bfloat162_rn(a, b);
    return *reinterpret_cast<unsigned*>(&h);
}
__device__ __forceinline__ unsigned pack_bf16_lo(float a, float b) {
    float ra = a - __bfloat162float(__float2bfloat16(a));
    float rb = b - __bfloat162float(__float2bfloat16(b));
    __nv_bfloat162 h = __floats2bfloat162_rn(ra, rb);
    return *reinterpret_cast<unsigned*>(&h);
}

// scratch (device globals: no allocation allowed)
__device__ float g_q [M_*A_];        // [b][s][a], pre-scaled by 1/sqrt(A)
__device__ float g_kt[B_*A_*S_];     // [b][a][s]  (K transposed)
__device__ float g_v [M_*A_];        // [b][s][a]

// ---------------------------------------------------------------------------
// Projection via mma.sync bf16 3-split: y[8192,128] = x @ W^T.
// grid (64 M-tiles, 3 which), block 256 (8 warps, 4 row-groups x 2 col-halves).
// Warp: 32 rows x 64 cols. K chunks of 64: LDG -> bf16 hi/lo -> smem
// [128][72 bf16] (pitch 36 words: fragment LDS (4g+t)%32 conflict-free),
// 4 k-steps x (2 row-tiles x 8 n-tiles x 3 products) mma.m16n8k16.
// ---------------------------------------------------------------------------
#define PP 36                 // tile pitch in 32-bit words (72 bf16)
#define TILE_W (128 * PP)     // words per tile
#define DP 132                // Dsm pitch (floats)
#define PROJ_SMEM (4 * TILE_W * 4)   // 73728 B (Dsm 128*132*4=67584 fits in reuse)

__global__ __launch_bounds__(256, 2) void proj_mma(
    const float* __restrict__ x,
    const float* __restrict__ Wk,
    const float* __restrict__ Wq,
    const float* __restrict__ Wv)
{
    extern __shared__ unsigned smu[];
    unsigned* x_hi = smu;
    unsigned* x_lo = smu + TILE_W;
    unsigned* w_hi = smu + 2 * TILE_W;
    unsigned* w_lo = smu + 3 * TILE_W;

    const int which = blockIdx.y;               // 0=K, 1=Q, 2=V
    const float* __restrict__ W = (which == 0) ? Wk : ((which == 1) ? Wq : Wv);
    const int m0   = blockIdx.x * 128;
    const int tid  = threadIdx.x;
    const int wid  = tid >> 5;
    const int lane = tid & 31;
    const int wr   = wid >> 1;            // row group: rows wr*32..+31
    const int wc   = wid & 1;             // col half:  cols wc*64..+63
    const int g    = lane >> 2;           // 0..7
    const int t    = lane & 3;            // 0..3

    float acc[2][8][4];                    // [rowtile][ntile][frag]
#pragma unroll
    for (int rt = 0; rt < 2; rt++)
#pragma unroll
        for (int nt = 0; nt < 8; nt++)
#pragma unroll
            for (int q = 0; q < 4; q++) acc[rt][nt][q] = 0.f;

    const int row  = tid >> 1;            // 0..127 (x M-row / W N-row)
    const int half = tid & 1;             // cols half*32..+31 of the 64-chunk

    for (int c = 0; c < 16; c++) {
        const int kt = c * 64;
        __syncthreads();   // previous chunk's MMAs done reading tiles

        // stage: LDG + bf16 hi/lo split + STS
        {
            const float* px = &x[(size_t)(m0 + row) * E_ + kt + half * 32];
            const float* pw = &W[(size_t)row * E_ + kt + half * 32];
            const int wbase = row * PP + half * 16;
#pragma unroll
            for (int u = 0; u < 8; u++) {
                float4 xv = *(const float4*)(px + u * 4);
                float4 wv = *(const float4*)(pw + u * 4);
                const int wo = wbase + u * 2;
                x_hi[wo]     = pack_bf16_hi(xv.x, xv.y);
                x_hi[wo + 1] = pack_bf16_hi(xv.z, xv.w);
                x_lo[wo]     = pack_bf16_lo(xv.x, xv.y);
                x_lo[wo + 1] = pack_bf16_lo(xv.z, xv.w);
                w_hi[wo]     = pack_bf16_hi(wv.x, wv.y);
                w_hi[wo + 1] = pack_bf16_hi(wv.z, wv.w);
                w_lo[wo]     = pack_bf16_lo(wv.x, wv.y);
                w_lo[wo + 1] = pack_bf16_lo(wv.z, wv.w);
            }
        }
        __syncthreads();

        // 4 k16-steps
#pragma unroll
        for (int ks = 0; ks < 4; ks++) {
            const int kw = ks * 8;   // word offset of this k-step
            unsigned ah[2][4], al[2][4];
#pragma unroll
            for (int rt = 0; rt < 2; rt++) {
                const int rb = wr * 32 + rt * 16;
                const int r0 = (rb + g) * PP + kw + t;
                const int r1 = (rb + g + 8) * PP + kw + t;
                ah[rt][0] = x_hi[r0];     ah[rt][1] = x_hi[r1];
                ah[rt][2] = x_hi[r0 + 4]; ah[rt][3] = x_hi[r1 + 4];
                al[rt][0] = x_lo[r0];     al[rt][1] = x_lo[r1];
                al[rt][2] = x_lo[r0 + 4]; al[rt][3] = x_lo[r1 + 4];
            }
#pragma unroll
            for (int nt = 0; nt < 8; nt++) {
                const int nb = wc * 64 + nt * 8;
                const int b0 = (nb + g) * PP + kw + t;
                unsigned bh[2] = { w_hi[b0], w_hi[b0 + 4] };
                unsigned bl[2] = { w_lo[b0], w_lo[b0 + 4] };
#pragma unroll
                for (int rt = 0; rt < 2; rt++) {
                    mma16816(acc[rt][nt], ah[rt], bh);
                    mma16816(acc[rt][nt], ah[rt], bl);
                    mma16816(acc[rt][nt], al[rt], bh);
                }
            }
        }
    }

    __syncthreads();   // all MMAs done; reuse smem as fp32 Dsm

    float* Dsm = (float*)smu;
    {
#pragma unroll
        for (int rt = 0; rt < 2; rt++) {
#pragma unroll
            for (int nt = 0; nt < 8; nt++) {
                const int rowA = wr * 32 + rt * 16 + g;
                const int col  = wc * 64 + nt * 8 + 2 * t;
                *(float2*)&Dsm[rowA * DP + col] =
                    make_float2(acc[rt][nt][0], acc[rt][nt][1]);
                *(float2*)&Dsm[(rowA + 8) * DP + col] =
                    make_float2(acc[rt][nt][2], acc[rt][nt][3]);
            }
        }
    }
    __syncthreads();

    // write out
    const int bb = m0 >> 11;
    const int s0 = m0 & (S_ - 1);
    if (which == 0) {
        // K transposed: g_kt[(b*128+n)*2048 + s]
        const int n  = tid >> 1;
        const int r0 = (tid & 1) * 64;
#pragma unroll
        for (int gi = 0; gi < 16; gi++) {
            float4 v;
            v.x = Dsm[(r0 + 4*gi + 0) * DP + n];
            v.y = Dsm[(r0 + 4*gi + 1) * DP + n];
            v.z = Dsm[(r0 + 4*gi + 2) * DP + n];
            v.w = Dsm[(r0 + 4*gi + 3) * DP + n];
            *(float4*)&g_kt[(size_t)(bb * A_ + n) * S_ + s0 + r0 + 4*gi] = v;
        }
    } else {
        const float sc = (which == 1) ? 0.08838834764831843f : 1.0f;
        float* dst = (which == 1) ? g_q : g_v;
        const int rr = tid >> 1;
        const int cb = (tid & 1) * 64;
        const float* sp = &Dsm[rr * DP + cb];
        float* gp = &dst[(size_t)(m0 + rr) * A_ + cb];
#pragma unroll
        for (int u = 0; u < 16; u++) {
            float4 v = *(const float4*)(sp + u * 4);
            v.x *= sc; v.y *= sc; v.z *= sc; v.w *= sc;
            *(float4*)(gp + u * 4) = v;
        }
    }
}

// ---------------------------------------------------------------------------
// Flash attention (causal), fp32 via FFMA2 — proven R8 config (291.9 us).
// BM=32, BN=128. grid (64,4) longest-first. block 256.
// ---------------------------------------------------------------------------
#define BM 32
#define BN 128
#define QP 132
#define TP 36

#define ATTN_SMEM ((36 + 132 + 132 + 36) * 128 * 4)

__global__ __launch_bounds__(256, 1) void attn_kernel(float* __restrict__ out)
{
    extern __shared__ float sm[];
    float* q_t = sm;                    // [128][TP]   q_t[d][row]
    float* k_s = q_t + 128 * TP;        // [128][QP]   k_s[d][key]
    float* v_s = k_s + 128 * QP;        // [128][QP]   v_s[key][d]
    float* p_t = v_s + 128 * QP;        // [128][TP]   p_t[key][row]
    __shared__ float red_m[2][32];
    __shared__ float red_s[2][32];

    const int qt  = 63 - blockIdx.x;    // longest CTAs first
    const int b   = blockIdx.y;
    const int q0  = qt * BM;
    const int tid = threadIdx.x;
    const int w   = tid >> 5;
    const int l   = tid & 31;

    const int half    = w & 1;
    const int rg      = w >> 1;
    const int rh      = l >> 4;
    const int rowbase = rg * 8 + rh * 4;
    const int cl      = half * 64 + (l & 15) * 4;

    {
        const int row = tid >> 3;
        const int cb  = (tid & 7) * 16;
        const float* gq = &g_q[(b * S_ + q0 + row) * A_ + cb];
#pragma unroll
        for (int u = 0; u < 4; u++) {
            float4 qv = *(const float4*)(gq + u * 4);
            q_t[(cb + u * 4 + 0) * TP + row] = qv.x;
            q_t[(cb + u * 4 + 1) * TP + row] = qv.y;
            q_t[(cb + u * 4 + 2) * TP + row] = qv.z;
            q_t[(cb + u * 4 + 3) * TP + row] = qv.w;
        }
    }

    float m_i[4], l_i[4];
    u64 o2[2][2][2];
#pragma unroll
    for (int i = 0; i < 4; i++) { m_i[i] = -1e30f; l_i[i] = 0.f; }
#pragma unroll
    for (int rp = 0; rp < 2; rp++)
#pragma unroll
        for (int cp = 0; cp < 2; cp++) { o2[rp][cp][0] = 0ull; o2[rp][cp][1] = 0ull; }

    const int hrow = tid >> 1;
    const int hcb  = (tid & 1) * 64;
    const int ntiles = (qt >> 2) + 1;

    for (int t = 0; t < ntiles; t++) {
        const int kb = t * BN;

        __syncthreads();
        {
            const float* gk = &g_kt[(b * A_ + hrow) * S_ + kb + hcb];
            float* dk = &k_s[hrow * QP + hcb];
#pragma unroll
            for (int u = 0; u < 16; u++)
                *(float4*)(dk + u * 4) = *(const float4*)(gk + u * 4);
            const float* gv = &g_v[(b * S_ + kb + hrow) * A_ + hcb];
            float* dv = &v_s[hrow * QP + hcb];
#pragma unroll
            for (int u = 0; u < 16; u++)
                *(float4*)(dv + u * 4) = *(const float4*)(gv + u * 4);
        }
        __syncthreads();

        u64 s2[2][2][2];
#pragma unroll
        for (int rp = 0; rp < 2; rp++)
#pragma unroll
            for (int cp = 0; cp < 2; cp++) { s2[rp][cp][0] = 0ull; s2[rp][cp][1] = 0ull; }

#pragma unroll 4
        for (int kk = 0; kk < 128; kk++) {
            ulonglong2 aq = *(const ulonglong2*)&q_t[kk * TP + rowbase];
            ulonglong2 bk = *(const ulonglong2*)&k_s[kk * QP + cl];
            u64 b0s = swap2(bk.x);
            u64 b1s = swap2(bk.y);
            ffma2(s2[0][0][0], aq.x, bk.x);
            ffma2(s2[0][0][1], aq.x, b0s);
            ffma2(s2[0][1][0], aq.x, bk.y);
            ffma2(s2[0][1][1], aq.x, b1s);
            ffma2(s2[1][0][0], aq.y, bk.x);
            ffma2(s2[1][0][1], aq.y, b0s);
            ffma2(s2[1][1][0], aq.y, bk.y);
            ffma2(s2[1][1][1], aq.y, b1s);
        }

        float s[4][4];
#pragma unroll
        for (int rp = 0; rp < 2; rp++)
#pragma unroll
            for (int cp = 0; cp < 2; cp++) {
                float a0, a1, b0, b1;
                unpack2(s2[rp][cp][0], a0, a1);
                unpack2(s2[rp][cp][1], b0, b1);
                s[2*rp  ][2*cp  ] = a0;
                s[2*rp+1][2*cp+1] = a1;
                s[2*rp  ][2*cp+1] = b0;
                s[2*rp+1][2*cp  ] = b1;
            }

        if (t == ntiles - 1) {
#pragma unroll
            for (int i = 0; i < 4; i++) {
                const int qg = q0 + rowbase + i;
#pragma unroll
                for (int j = 0; j < 4; j++)
                    if (kb + cl + j > qg) s[i][j] = -1e30f;
            }
        }

        float pm[4], al[4], ps[4], mnew[4], p[4][4];
#pragma unroll
        for (int i = 0; i < 4; i++) {
            float mx = fmaxf(fmaxf(s[i][0], s[i][1]), fmaxf(s[i][2], s[i][3]));
#pragma unroll
            for (int off = 8; off > 0; off >>= 1)
                mx = fmaxf(mx, __shfl_xor_sync(0xffffffffu, mx, off));
            pm[i] = mx;
        }
        if ((l & 15) == 0) {
#pragma unroll
            for (int i = 0; i < 4; i++) red_m[half][rowbase + i] = pm[i];
        }
        __syncthreads();
#pragma unroll
        for (int i = 0; i < 4; i++) {
            const float om = red_m[half ^ 1][rowbase + i];
            mnew[i] = fmaxf(m_i[i], fmaxf(pm[i], om));
            al[i]   = __expf(m_i[i] - mnew[i]);
            p[i][0] = __expf(s[i][0] - mnew[i]);
            p[i][1] = __expf(s[i][1] - mnew[i]);
            p[i][2] = __expf(s[i][2] - mnew[i]);
            p[i][3] = __expf(s[i][3] - mnew[i]);
            float ss = (p[i][0] + p[i][1]) + (p[i][2] + p[i][3]);
#pragma unroll
            for (int off = 8; off > 0; off >>= 1)
                ss += __shfl_xor_sync(0xffffffffu, ss, off);
            ps[i] = ss;
            m_i[i] = mnew[i];
        }
#pragma unroll
        for (int j = 0; j < 4; j++)
            *(float4*)&p_t[(cl + j) * TP + rowbase] =
                make_float4(p[0][j], p[1][j], p[2][j], p[3][j]);
        if ((l & 15) == 0) {
#pragma unroll
            for (int i = 0; i < 4; i++) red_s[half][rowbase + i] = ps[i];
        }
        {
            u64 a01 = pack2(al[0], al[1]);
            u64 a23 = pack2(al[2], al[3]);
#pragma unroll
            for (int cp = 0; cp < 2; cp++) {
                fmul2(o2[0][cp][0], a01); fmul2(o2[0][cp][1], a01);
                fmul2(o2[1][cp][0], a23); fmul2(o2[1][cp][1], a23);
            }
        }
        __syncthreads();
#pragma unroll
        for (int i = 0; i < 4; i++)
            l_i[i] = l_i[i] * al[i] + ps[i] + red_s[half ^ 1][rowbase + i];

#pragma unroll 4
        for (int kk = 0; kk < 128; kk++) {
            ulonglong2 ap = *(const ulonglong2*)&p_t[kk * TP + rowbase];
            ulonglong2 bv = *(const ulonglong2*)&v_s[kk * QP + cl];
            u64 b0s = swap2(bv.x);
            u64 b1s = swap2(bv.y);
            ffma2(o2[0][0][0], ap.x, bv.x);
            ffma2(o2[0][0][1], ap.x, b0s);
            ffma2(o2[0][1][0], ap.x, bv.y);
            ffma2(o2[0][1][1], ap.x, b1s);
            ffma2(o2[1][0][0], ap.y, bv.x);
            ffma2(o2[1][0][1], ap.y, b0s);
            ffma2(o2[1][1][0], ap.y, bv.y);
            ffma2(o2[1][1][1], ap.y, b1s);
        }
    }

    float o[4][4];
#pragma unroll
    for (int rp = 0; rp < 2; rp++)
#pragma unroll
        for (int cp = 0; cp < 2; cp++) {
            float a0, a1, b0, b1;
            unpack2(o2[rp][cp][0], a0, a1);
            unpack2(o2[rp][cp][1], b0, b1);
            o[2*rp  ][2*cp  ] = a0;
            o[2*rp+1][2*cp+1] = a1;
            o[2*rp  ][2*cp+1] = b0;
            o[2*rp+1][2*cp  ] = b1;
        }
#pragma unroll
    for (int i = 0; i < 4; i++) {
        const float inv = 1.f / l_i[i];
        float4 res;
        res.x = o[i][0] * inv;
        res.y = o[i][1] * inv;
        res.z = o[i][2] * inv;
        res.w = o[i][3] * inv;
        *(float4*)&out[(b * S_ + q0 + rowbase + i) * A_ + cl] = res;
    }
}

// ---------------------------------------------------------------------------
extern "C" void kernel_launch(void* const* d_in, const int* in_sizes, int n_in,
                              void* d_out, int out_size)
{
    const float* x  = (const float*)d_in[0];   // embedded [4,2048,1024]
    const float* Wk = (const float*)d_in[1];   // [128,1024]
    const float* Wq = (const float*)d_in[2];
    const float* Wv = (const float*)d_in[3];
    float* out = (float*)d_out;                // [4,2048,128] fp32

    cudaFuncSetAttribute(proj_mma,
                         cudaFuncAttributeMaxDynamicSharedMemorySize,
                         PROJ_SMEM);
    cudaFuncSetAttribute(attn_kernel,
                         cudaFuncAttributeMaxDynamicSharedMemorySize,
                         ATTN_SMEM);

    proj_mma<<<dim3(64, 3), 256, PROJ_SMEM>>>(x, Wk, Wq, Wv);
    attn_kernel<<<dim3(64, B_), 256, ATTN_SMEM>>>(out);
}

// round 12
// speedup vs baseline: 1.7064x; 1.3126x over previous
#include <cuda_runtime.h>
#include <cuda_bf16.h>
#include <cstdint>

#define B_ 4
#define S_ 2048
#define E_ 1024
#define A_ 128
#define M_ (B_*S_)   // 8192

// ---- mma.sync bf16 (base ISA, compiles for compute_103) ----
__device__ __forceinline__ void mma16816(float* d, const unsigned* a, const unsigned* b) {
    asm volatile(
        "mma.sync.aligned.m16n8k16.row.col.f32.bf16.bf16.f32 "
        "{%0,%1,%2,%3}, {%4,%5,%6,%7}, {%8,%9}, {%0,%1,%2,%3};"
        : "+f"(d[0]), "+f"(d[1]), "+f"(d[2]), "+f"(d[3])
        : "r"(a[0]), "r"(a[1]), "r"(a[2]), "r"(a[3]), "r"(b[0]), "r"(b[1]));
}

__device__ __forceinline__ unsigned pack_bf16_hi(float a, float b) {
    __nv_bfloat162 h = __floats2bfloat162_rn(a, b);
    return *reinterpret_cast<unsigned*>(&h);
}
__device__ __forceinline__ unsigned pack_bf16_lo(float a, float b) {
    float ra = a - __bfloat162float(__float2bfloat16(a));
    float rb = b - __bfloat162float(__float2bfloat16(b));
    __nv_bfloat162 h = __floats2bfloat162_rn(ra, rb);
    return *reinterpret_cast<unsigned*>(&h);
}

// scratch (device globals: no allocation allowed)
__device__ __nv_bfloat16 g_xhi[M_*E_], g_xlo[M_*E_];      // x hi/lo split
__device__ __nv_bfloat16 g_whi[3*A_*E_], g_wlo[3*A_*E_];  // Wk|Wq|Wv hi/lo
__device__ __nv_bfloat16 g_qhi[M_*A_], g_qlo[M_*A_];      // Q (scaled) [m][a]
__device__ __nv_bfloat16 g_khi[M_*A_], g_klo[M_*A_];      // K [m][a]
__device__ __nv_bfloat16 g_vthi[M_*A_], g_vtlo[M_*A_];    // V^T [b][a][s]

// ---------------------------------------------------------------------------
// split_xw: one-time bf16 hi/lo split of x and the three W matrices.
// ---------------------------------------------------------------------------
__global__ __launch_bounds__(256) void split_xw(
    const float* __restrict__ x,
    const float* __restrict__ Wk,
    const float* __restrict__ Wq,
    const float* __restrict__ Wv)
{
    const int NX  = M_ * E_ / 4;      // float4 count for x
    const int NW1 = A_ * E_ / 4;      // per W
    const int NT  = NX + 3 * NW1;
    for (int i = blockIdx.x * blockDim.x + threadIdx.x; i < NT;
         i += gridDim.x * blockDim.x) {
        const float4* src;
        __nv_bfloat16 *dh, *dl;
        int idx;
        if (i < NX) {
            src = (const float4*)x; idx = i; dh = g_xhi; dl = g_xlo;
        } else {
            int j = i - NX; int w = j / NW1; idx = j - w * NW1;
            src = (const float4*)(w == 0 ? Wk : (w == 1 ? Wq : Wv));
            dh = g_whi + (size_t)w * A_ * E_;
            dl = g_wlo + (size_t)w * A_ * E_;
        }
        float4 v = src[idx];
        uint2 h, l;
        h.x = pack_bf16_hi(v.x, v.y); h.y = pack_bf16_hi(v.z, v.w);
        l.x = pack_bf16_lo(v.x, v.y); l.y = pack_bf16_lo(v.z, v.w);
        *(uint2*)(dh + (size_t)idx * 4) = h;
        *(uint2*)(dl + (size_t)idx * 4) = l;
    }
}

// ---------------------------------------------------------------------------
// Projection via mma.sync bf16 3-split (R11-proven MMA core; staging now LDGs
// precomputed bf16). grid (64 M-tiles, 3 which), block 256 (8 warps 4x2).
// Epilogue writes bf16 hi/lo outputs directly: Q (scaled), K, V^T.
// ---------------------------------------------------------------------------
#define PP 36                 // tile pitch in 32-bit words
#define TILE_W (128 * PP)
#define DP 132
#define PROJ_SMEM (4 * TILE_W * 4)   // 73728 B

__global__ __launch_bounds__(256, 2) void proj_mma2()
{
    extern __shared__ unsigned smu[];
    unsigned* x_hi = smu;
    unsigned* x_lo = smu + TILE_W;
    unsigned* w_hi = smu + 2 * TILE_W;
    unsigned* w_lo = smu + 3 * TILE_W;

    const int which = blockIdx.y;               // 0=K, 1=Q, 2=V
    const int m0   = blockIdx.x * 128;
    const int tid  = threadIdx.x;
    const int wid  = tid >> 5;
    const int lane = tid & 31;
    const int wr   = wid >> 1;
    const int wc   = wid & 1;
    const int g    = lane >> 2;
    const int t    = lane & 3;

    const __nv_bfloat16* wbh = g_whi + (size_t)which * A_ * E_;
    const __nv_bfloat16* wbl = g_wlo + (size_t)which * A_ * E_;

    float acc[2][8][4];
#pragma unroll
    for (int rt = 0; rt < 2; rt++)
#pragma unroll
        for (int nt = 0; nt < 8; nt++)
#pragma unroll
            for (int q = 0; q < 4; q++) acc[rt][nt][q] = 0.f;

    const int row  = tid >> 1;
    const int half = tid & 1;

    for (int c = 0; c < 16; c++) {
        __syncthreads();
        {
            const size_t xe = (size_t)(m0 + row) * E_ + c * 64 + half * 32;
            const size_t we = (size_t)row * E_ + c * 64 + half * 32;
            const uint4* sxh = (const uint4*)(g_xhi + xe);
            const uint4* sxl = (const uint4*)(g_xlo + xe);
            const uint4* swh = (const uint4*)(wbh + we);
            const uint4* swl = (const uint4*)(wbl + we);
            const int wb = row * PP + half * 16;
#pragma unroll
            for (int u = 0; u < 4; u++) {
                *(uint4*)&x_hi[wb + 4 * u] = sxh[u];
                *(uint4*)&x_lo[wb + 4 * u] = sxl[u];
                *(uint4*)&w_hi[wb + 4 * u] = swh[u];
                *(uint4*)&w_lo[wb + 4 * u] = swl[u];
            }
        }
        __syncthreads();

#pragma unroll
        for (int ks = 0; ks < 4; ks++) {
            const int kw = ks * 8;
            unsigned ah[2][4], al[2][4];
#pragma unroll
            for (int rt = 0; rt < 2; rt++) {
                const int rb = wr * 32 + rt * 16;
                const int r0 = (rb + g) * PP + kw + t;
                const int r1 = (rb + g + 8) * PP + kw + t;
                ah[rt][0] = x_hi[r0];     ah[rt][1] = x_hi[r1];
                ah[rt][2] = x_hi[r0 + 4]; ah[rt][3] = x_hi[r1 + 4];
                al[rt][0] = x_lo[r0];     al[rt][1] = x_lo[r1];
                al[rt][2] = x_lo[r0 + 4]; al[rt][3] = x_lo[r1 + 4];
            }
#pragma unroll
            for (int nt = 0; nt < 8; nt++) {
                const int nb = wc * 64 + nt * 8;
                const int b0 = (nb + g) * PP + kw + t;
                unsigned bh[2] = { w_hi[b0], w_hi[b0 + 4] };
                unsigned bl[2] = { w_lo[b0], w_lo[b0 + 4] };
#pragma unroll
                for (int rt = 0; rt < 2; rt++) {
                    mma16816(acc[rt][nt], ah[rt], bh);
                    mma16816(acc[rt][nt], ah[rt], bl);
                    mma16816(acc[rt][nt], al[rt], bh);
                }
            }
        }
    }

    __syncthreads();   // reuse smem as fp32 Dsm
    float* Dsm = (float*)smu;
#pragma unroll
    for (int rt = 0; rt < 2; rt++) {
#pragma unroll
        for (int nt = 0; nt < 8; nt++) {
            const int rowA = wr * 32 + rt * 16 + g;
            const int col  = wc * 64 + nt * 8 + 2 * t;
            *(float2*)&Dsm[rowA * DP + col] =
                make_float2(acc[rt][nt][0], acc[rt][nt][1]);
            *(float2*)&Dsm[(rowA + 8) * DP + col] =
                make_float2(acc[rt][nt][2], acc[rt][nt][3]);
        }
    }
    __syncthreads();

    // write bf16 hi/lo outputs
    const int bb = m0 >> 11;
    const int s0 = m0 & (S_ - 1);
    if (which == 2) {
        // V^T: [b][a][s]
        const int n  = tid >> 1;
        const int r0 = (tid & 1) * 64;
        const size_t base = ((size_t)(bb * A_ + n)) * S_ + s0 + r0;
#pragma unroll
        for (int u = 0; u < 8; u++) {
            float f[8];
#pragma unroll
            for (int j = 0; j < 8; j++) f[j] = Dsm[(r0 + 8 * u + j) * DP + n];
            uint4 h = make_uint4(pack_bf16_hi(f[0], f[1]), pack_bf16_hi(f[2], f[3]),
                                 pack_bf16_hi(f[4], f[5]), pack_bf16_hi(f[6], f[7]));
            uint4 l = make_uint4(pack_bf16_lo(f[0], f[1]), pack_bf16_lo(f[2], f[3]),
                                 pack_bf16_lo(f[4], f[5]), pack_bf16_lo(f[6], f[7]));
            *(uint4*)(g_vthi + base + 8 * u) = h;
            *(uint4*)(g_vtlo + base + 8 * u) = l;
        }
    } else {
        const float sc = (which == 1) ? 0.08838834764831843f : 1.0f;  // 1/sqrt(128)
        __nv_bfloat16* dsth = (which == 1) ? g_qhi : g_khi;
        __nv_bfloat16* dstl = (which == 1) ? g_qlo : g_klo;
        const int rr = tid >> 1;
        const int cb = (tid & 1) * 64;
        const float* sp = &Dsm[rr * DP + cb];
        const size_t base = (size_t)(m0 + rr) * A_ + cb;
#pragma unroll
        for (int u = 0; u < 8; u++) {
            float f[8];
#pragma unroll
            for (int j = 0; j < 8; j++) f[j] = sp[8 * u + j] * sc;
            uint4 h = make_uint4(pack_bf16_hi(f[0], f[1]), pack_bf16_hi(f[2], f[3]),
                                 pack_bf16_hi(f[4], f[5]), pack_bf16_hi(f[6], f[7]));
            uint4 l = make_uint4(pack_bf16_lo(f[0], f[1]), pack_bf16_lo(f[2], f[3]),
                                 pack_bf16_lo(f[4], f[5]), pack_bf16_lo(f[6], f[7]));
            *(uint4*)(dsth + base + 8 * u) = h;
            *(uint4*)(dstl + base + 8 * u) = l;
        }
    }
}

// ---------------------------------------------------------------------------
// Flash attention (causal) via mma.sync bf16 3-split.
// BM=64, BN=64, block 128 (4 row-warps x 16 rows; warp spans all keys/dims).
// S D-frags reused directly as PV A-frags (no P smem round-trip).
// grid (32 q-tiles, 4 batches), longest-first.
// ---------------------------------------------------------------------------
#define AQP 68                 // q/k tile pitch (words); 68%32==4 -> CF frags
#define AVP 36                 // v^T tile pitch
#define QW (64 * AQP)          // 4352 words
#define VW (128 * AVP)         // 4608 words
#define ATTN_SMEM ((4 * QW + 2 * VW) * 4)   // 106496 B

__global__ __launch_bounds__(128) void attn_mma(float* __restrict__ out)
{
    extern __shared__ unsigned smw[];
    unsigned* qh = smw;
    unsigned* ql = qh + QW;
    unsigned* kh = ql + QW;
    unsigned* kl = kh + QW;
    unsigned* vh = kl + QW;
    unsigned* vl = vh + VW;

    const int qt  = 31 - blockIdx.x;   // longest CTAs first
    const int b   = blockIdx.y;
    const int q0  = qt * 64;
    const int tid = threadIdx.x;
    const int wr  = tid >> 5;
    const int lane = tid & 31;
    const int g   = lane >> 2;
    const int t   = lane & 3;

    // stage Q (64 rows x 128 d, hi/lo)
    {
        const int row = tid >> 1, hf = tid & 1;
        const size_t e = (size_t)(b * S_ + q0 + row) * A_ + hf * 64;
        const uint4* sh = (const uint4*)(g_qhi + e);
        const uint4* sl = (const uint4*)(g_qlo + e);
        const int wb = row * AQP + hf * 32;
#pragma unroll
        for (int u = 0; u < 8; u++) {
            *(uint4*)&qh[wb + 4 * u] = sh[u];
            *(uint4*)&ql[wb + 4 * u] = sl[u];
        }
    }

    float o[16][4];
#pragma unroll
    for (int nt = 0; nt < 16; nt++)
#pragma unroll
        for (int q = 0; q < 4; q++) o[nt][q] = 0.f;
    float m0r = -1e30f, m1r = -1e30f, l0r = 0.f, l1r = 0.f;

    const int ntiles = qt + 1;

    for (int tt = 0; tt < ntiles; tt++) {
        const int kb = tt * 64;
        __syncthreads();   // Q ready (tt=0) / prev tile consumed
        {
            const int row = tid >> 1, hf = tid & 1;
            const size_t e = (size_t)(b * S_ + kb + row) * A_ + hf * 64;
            const uint4* sh = (const uint4*)(g_khi + e);
            const uint4* sl = (const uint4*)(g_klo + e);
            const int wb = row * AQP + hf * 32;
#pragma unroll
            for (int u = 0; u < 8; u++) {
                *(uint4*)&kh[wb + 4 * u] = sh[u];
                *(uint4*)&kl[wb + 4 * u] = sl[u];
            }
            const size_t ev = (size_t)(b * A_ + tid) * S_ + kb;
            const uint4* vsh = (const uint4*)(g_vthi + ev);
            const uint4* vsl = (const uint4*)(g_vtlo + ev);
            const int vb = tid * AVP;
#pragma unroll
            for (int u = 0; u < 8; u++) {
                *(uint4*)&vh[vb + 4 * u] = vsh[u];
                *(uint4*)&vl[vb + 4 * u] = vsl[u];
            }
        }
        __syncthreads();

        // ---- S = Q K^T (3-split) ----
        float s[8][4];
#pragma unroll
        for (int nt = 0; nt < 8; nt++)
#pragma unroll
            for (int q = 0; q < 4; q++) s[nt][q] = 0.f;

#pragma unroll
        for (int ks = 0; ks < 8; ks++) {
            const int r0 = (wr * 16 + g) * AQP + ks * 8 + t;
            const int r1 = r0 + 8 * AQP;
            unsigned ah[4] = { qh[r0], qh[r1], qh[r0 + 4], qh[r1 + 4] };
            unsigned al_[4] = { ql[r0], ql[r1], ql[r0 + 4], ql[r1 + 4] };
#pragma unroll
            for (int nt = 0; nt < 8; nt++) {
                const int bw = (nt * 8 + g) * AQP + ks * 8 + t;
                unsigned bh[2] = { kh[bw], kh[bw + 4] };
                unsigned bl[2] = { kl[bw], kl[bw + 4] };
                mma16816(s[nt], ah, bh);
                mma16816(s[nt], ah, bl);
                mma16816(s[nt], al_, bh);
            }
        }

        // causal mask (only the diagonal tile, kb == q0)
        if (tt == ntiles - 1) {
            const int row0 = q0 + wr * 16 + g;
#pragma unroll
            for (int nt = 0; nt < 8; nt++) {
                const int c0 = kb + nt * 8 + 2 * t;
                if (c0     > row0)     s[nt][0] = -1e30f;
                if (c0 + 1 > row0)     s[nt][1] = -1e30f;
                if (c0     > row0 + 8) s[nt][2] = -1e30f;
                if (c0 + 1 > row0 + 8) s[nt][3] = -1e30f;
            }
        }

        // ---- online softmax (rows g and g+8; reduce over 4-lane t-group) ----
        float mx0 = -1e30f, mx1 = -1e30f;
#pragma unroll
        for (int nt = 0; nt < 8; nt++) {
            mx0 = fmaxf(mx0, fmaxf(s[nt][0], s[nt][1]));
            mx1 = fmaxf(mx1, fmaxf(s[nt][2], s[nt][3]));
        }
        mx0 = fmaxf(mx0, __shfl_xor_sync(0xffffffffu, mx0, 1));
        mx0 = fmaxf(mx0, __shfl_xor_sync(0xffffffffu, mx0, 2));
        mx1 = fmaxf(mx1, __shfl_xor_sync(0xffffffffu, mx1, 1));
        mx1 = fmaxf(mx1, __shfl_xor_sync(0xffffffffu, mx1, 2));
        const float mn0 = fmaxf(m0r, mx0), mn1 = fmaxf(m1r, mx1);
        const float a0 = __expf(m0r - mn0), a1 = __expf(m1r - mn1);
        float sum0 = 0.f, sum1 = 0.f;
#pragma unroll
        for (int nt = 0; nt < 8; nt++) {
            s[nt][0] = __expf(s[nt][0] - mn0);
            s[nt][1] = __expf(s[nt][1] - mn0);
            s[nt][2] = __expf(s[nt][2] - mn1);
            s[nt][3] = __expf(s[nt][3] - mn1);
            sum0 += s[nt][0] + s[nt][1];
            sum1 += s[nt][2] + s[nt][3];
        }
        sum0 += __shfl_xor_sync(0xffffffffu, sum0, 1);
        sum0 += __shfl_xor_sync(0xffffffffu, sum0, 2);
        sum1 += __shfl_xor_sync(0xffffffffu, sum1, 1);
        sum1 += __shfl_xor_sync(0xffffffffu, sum1, 2);
        l0r = l0r * a0 + sum0;  l1r = l1r * a1 + sum1;
        m0r = mn0;  m1r = mn1;

        // rescale O
#pragma unroll
        for (int nt = 0; nt < 16; nt++) {
            o[nt][0] *= a0; o[nt][1] *= a0;
            o[nt][2] *= a1; o[nt][3] *= a1;
        }

        // ---- O += P V  (P A-frags straight from S regs) ----
#pragma unroll
        for (int ks2 = 0; ks2 < 4; ks2++) {
            unsigned pa_h[4], pa_l[4];
            pa_h[0] = pack_bf16_hi(s[2*ks2  ][0], s[2*ks2  ][1]);
            pa_h[1] = pack_bf16_hi(s[2*ks2  ][2], s[2*ks2  ][3]);
            pa_h[2] = pack_bf16_hi(s[2*ks2+1][0], s[2*ks2+1][1]);
            pa_h[3] = pack_bf16_hi(s[2*ks2+1][2], s[2*ks2+1][3]);
            pa_l[0] = pack_bf16_lo(s[2*ks2  ][0], s[2*ks2  ][1]);
            pa_l[1] = pack_bf16_lo(s[2*ks2  ][2], s[2*ks2  ][3]);
            pa_l[2] = pack_bf16_lo(s[2*ks2+1][0], s[2*ks2+1][1]);
            pa_l[3] = pack_bf16_lo(s[2*ks2+1][2], s[2*ks2+1][3]);
#pragma unroll
            for (int nt2 = 0; nt2 < 16; nt2++) {
                const int bw = (nt2 * 8 + g) * AVP + ks2 * 8 + t;
                unsigned bh[2] = { vh[bw], vh[bw + 4] };
                unsigned bl[2] = { vl[bw], vl[bw + 4] };
                mma16816(o[nt2], pa_h, bh);
                mma16816(o[nt2], pa_h, bl);
                mma16816(o[nt2], pa_l, bh);
            }
        }
    }

    // ---- epilogue ----
    const float i0 = 1.f / l0r, i1 = 1.f / l1r;
    const int row0 = b * S_ + q0 + wr * 16 + g;
#pragma unroll
    for (int nt2 = 0; nt2 < 16; nt2++) {
        const int c = nt2 * 8 + 2 * t;
        *(float2*)&out[(size_t)row0 * A_ + c] =
            make_float2(o[nt2][0] * i0, o[nt2][1] * i0);
        *(float2*)&out[(size_t)(row0 + 8) * A_ + c] =
            make_float2(o[nt2][2] * i1, o[nt2][3] * i1);
    }
}

// ---------------------------------------------------------------------------
extern "C" void kernel_launch(void* const* d_in, const int* in_sizes, int n_in,
                              void* d_out, int out_size)
{
    const float* x  = (const float*)d_in[0];   // embedded [4,2048,1024]
    const float* Wk = (const float*)d_in[1];   // [128,1024]
    const float* Wq = (const float*)d_in[2];
    const float* Wv = (const float*)d_in[3];
    float* out = (float*)d_out;                // [4,2048,128] fp32

    cudaFuncSetAttribute(proj_mma2,
                         cudaFuncAttributeMaxDynamicSharedMemorySize,
                         PROJ_SMEM);
    cudaFuncSetAttribute(attn_mma,
                         cudaFuncAttributeMaxDynamicSharedMemorySize,
                         ATTN_SMEM);

    split_xw<<<4096, 256>>>(x, Wk, Wq, Wv);
    proj_mma2<<<dim3(64, 3), 256, PROJ_SMEM>>>();
    attn_mma<<<dim3(32, 4), 128, ATTN_SMEM>>>(out);
}

// round 13
// speedup vs baseline: 2.7030x; 1.5841x over previous
#include <cuda_runtime.h>
#include <cuda_bf16.h>
#include <cstdint>

#define B_ 4
#define S_ 2048
#define E_ 1024
#define A_ 128
#define M_ (B_*S_)   // 8192

// ---- mma.sync bf16 (base ISA, compiles for compute_103) ----
__device__ __forceinline__ void mma16816(float* d, const unsigned* a, const unsigned* b) {
    asm volatile(
        "mma.sync.aligned.m16n8k16.row.col.f32.bf16.bf16.f32 "
        "{%0,%1,%2,%3}, {%4,%5,%6,%7}, {%8,%9}, {%0,%1,%2,%3};"
        : "+f"(d[0]), "+f"(d[1]), "+f"(d[2]), "+f"(d[3])
        : "r"(a[0]), "r"(a[1]), "r"(a[2]), "r"(a[3]), "r"(b[0]), "r"(b[1]));
}

__device__ __forceinline__ unsigned pack_bf16_hi(float a, float b) {
    __nv_bfloat162 h = __floats2bfloat162_rn(a, b);
    return *reinterpret_cast<unsigned*>(&h);
}
__device__ __forceinline__ unsigned pack_bf16_lo(float a, float b) {
    float ra = a - __bfloat162float(__float2bfloat16(a));
    float rb = b - __bfloat162float(__float2bfloat16(b));
    __nv_bfloat162 h = __floats2bfloat162_rn(ra, rb);
    return *reinterpret_cast<unsigned*>(&h);
}

// scratch (device globals: no allocation allowed)
__device__ __nv_bfloat16 g_xhi[M_*E_], g_xlo[M_*E_];      // x hi/lo split
__device__ __nv_bfloat16 g_whi[3*A_*E_], g_wlo[3*A_*E_];  // Wk|Wq|Wv hi/lo
__device__ __nv_bfloat16 g_qhi[M_*A_], g_qlo[M_*A_];      // Q (scaled) [m][a]
__device__ __nv_bfloat16 g_khi[M_*A_], g_klo[M_*A_];      // K [m][a]
__device__ __nv_bfloat16 g_vthi[M_*A_], g_vtlo[M_*A_];    // V^T [b][a][s]
__device__ float  g_po [4*32*4*64*128];                   // split-K partial O
__device__ float2 g_pml[4*32*4*64];                       // partial (m, l)

// ---------------------------------------------------------------------------
// split_xw: one-time bf16 hi/lo split of x and the three W matrices.
// ---------------------------------------------------------------------------
__global__ __launch_bounds__(256) void split_xw(
    const float* __restrict__ x,
    const float* __restrict__ Wk,
    const float* __restrict__ Wq,
    const float* __restrict__ Wv)
{
    const int NX  = M_ * E_ / 4;
    const int NW1 = A_ * E_ / 4;
    const int NT  = NX + 3 * NW1;
    for (int i = blockIdx.x * blockDim.x + threadIdx.x; i < NT;
         i += gridDim.x * blockDim.x) {
        const float4* src;
        __nv_bfloat16 *dh, *dl;
        int idx;
        if (i < NX) {
            src = (const float4*)x; idx = i; dh = g_xhi; dl = g_xlo;
        } else {
            int j = i - NX; int w = j / NW1; idx = j - w * NW1;
            src = (const float4*)(w == 0 ? Wk : (w == 1 ? Wq : Wv));
            dh = g_whi + (size_t)w * A_ * E_;
            dl = g_wlo + (size_t)w * A_ * E_;
        }
        float4 v = src[idx];
        uint2 h, l;
        h.x = pack_bf16_hi(v.x, v.y); h.y = pack_bf16_hi(v.z, v.w);
        l.x = pack_bf16_lo(v.x, v.y); l.y = pack_bf16_lo(v.z, v.w);
        *(uint2*)(dh + (size_t)idx * 4) = h;
        *(uint2*)(dl + (size_t)idx * 4) = l;
    }
}

// ---------------------------------------------------------------------------
// Projection via mma.sync bf16 3-split (R12-proven, unchanged).
// ---------------------------------------------------------------------------
#define PP 36
#define TILE_W (128 * PP)
#define DP 132
#define PROJ_SMEM (4 * TILE_W * 4)

__global__ __launch_bounds__(256, 2) void proj_mma2()
{
    extern __shared__ unsigned smu[];
    unsigned* x_hi = smu;
    unsigned* x_lo = smu + TILE_W;
    unsigned* w_hi = smu + 2 * TILE_W;
    unsigned* w_lo = smu + 3 * TILE_W;

    const int which = blockIdx.y;
    const int m0   = blockIdx.x * 128;
    const int tid  = threadIdx.x;
    const int wid  = tid >> 5;
    const int lane = tid & 31;
    const int wr   = wid >> 1;
    const int wc   = wid & 1;
    const int g    = lane >> 2;
    const int t    = lane & 3;

    const __nv_bfloat16* wbh = g_whi + (size_t)which * A_ * E_;
    const __nv_bfloat16* wbl = g_wlo + (size_t)which * A_ * E_;

    float acc[2][8][4];
#pragma unroll
    for (int rt = 0; rt < 2; rt++)
#pragma unroll
        for (int nt = 0; nt < 8; nt++)
#pragma unroll
            for (int q = 0; q < 4; q++) acc[rt][nt][q] = 0.f;

    const int row  = tid >> 1;
    const int half = tid & 1;

    for (int c = 0; c < 16; c++) {
        __syncthreads();
        {
            const size_t xe = (size_t)(m0 + row) * E_ + c * 64 + half * 32;
            const size_t we = (size_t)row * E_ + c * 64 + half * 32;
            const uint4* sxh = (const uint4*)(g_xhi + xe);
            const uint4* sxl = (const uint4*)(g_xlo + xe);
            const uint4* swh = (const uint4*)(wbh + we);
            const uint4* swl = (const uint4*)(wbl + we);
            const int wb = row * PP + half * 16;
#pragma unroll
            for (int u = 0; u < 4; u++) {
                *(uint4*)&x_hi[wb + 4 * u] = sxh[u];
                *(uint4*)&x_lo[wb + 4 * u] = sxl[u];
                *(uint4*)&w_hi[wb + 4 * u] = swh[u];
                *(uint4*)&w_lo[wb + 4 * u] = swl[u];
            }
        }
        __syncthreads();

#pragma unroll
        for (int ks = 0; ks < 4; ks++) {
            const int kw = ks * 8;
            unsigned ah[2][4], al[2][4];
#pragma unroll
            for (int rt = 0; rt < 2; rt++) {
                const int rb = wr * 32 + rt * 16;
                const int r0 = (rb + g) * PP + kw + t;
                const int r1 = (rb + g + 8) * PP + kw + t;
                ah[rt][0] = x_hi[r0];     ah[rt][1] = x_hi[r1];
                ah[rt][2] = x_hi[r0 + 4]; ah[rt][3] = x_hi[r1 + 4];
                al[rt][0] = x_lo[r0];     al[rt][1] = x_lo[r1];
                al[rt][2] = x_lo[r0 + 4]; al[rt][3] = x_lo[r1 + 4];
            }
#pragma unroll
            for (int nt = 0; nt < 8; nt++) {
                const int nb = wc * 64 + nt * 8;
                const int b0 = (nb + g) * PP + kw + t;
                unsigned bh[2] = { w_hi[b0], w_hi[b0 + 4] };
                unsigned bl[2] = { w_lo[b0], w_lo[b0 + 4] };
#pragma unroll
                for (int rt = 0; rt < 2; rt++) {
                    mma16816(acc[rt][nt], ah[rt], bh);
                    mma16816(acc[rt][nt], ah[rt], bl);
                    mma16816(acc[rt][nt], al[rt], bh);
                }
            }
        }
    }

    __syncthreads();
    float* Dsm = (float*)smu;
#pragma unroll
    for (int rt = 0; rt < 2; rt++) {
#pragma unroll
        for (int nt = 0; nt < 8; nt++) {
            const int rowA = wr * 32 + rt * 16 + g;
            const int col  = wc * 64 + nt * 8 + 2 * t;
            *(float2*)&Dsm[rowA * DP + col] =
                make_float2(acc[rt][nt][0], acc[rt][nt][1]);
            *(float2*)&Dsm[(rowA + 8) * DP + col] =
                make_float2(acc[rt][nt][2], acc[rt][nt][3]);
        }
    }
    __syncthreads();

    const int bb = m0 >> 11;
    const int s0 = m0 & (S_ - 1);
    if (which == 2) {
        const int n  = tid >> 1;
        const int r0 = (tid & 1) * 64;
        const size_t base = ((size_t)(bb * A_ + n)) * S_ + s0 + r0;
#pragma unroll
        for (int u = 0; u < 8; u++) {
            float f[8];
#pragma unroll
            for (int j = 0; j < 8; j++) f[j] = Dsm[(r0 + 8 * u + j) * DP + n];
            uint4 h = make_uint4(pack_bf16_hi(f[0], f[1]), pack_bf16_hi(f[2], f[3]),
                                 pack_bf16_hi(f[4], f[5]), pack_bf16_hi(f[6], f[7]));
            uint4 l = make_uint4(pack_bf16_lo(f[0], f[1]), pack_bf16_lo(f[2], f[3]),
                                 pack_bf16_lo(f[4], f[5]), pack_bf16_lo(f[6], f[7]));
            *(uint4*)(g_vthi + base + 8 * u) = h;
            *(uint4*)(g_vtlo + base + 8 * u) = l;
        }
    } else {
        const float sc = (which == 1) ? 0.08838834764831843f : 1.0f;
        __nv_bfloat16* dsth = (which == 1) ? g_qhi : g_khi;
        __nv_bfloat16* dstl = (which == 1) ? g_qlo : g_klo;
        const int rr = tid >> 1;
        const int cb = (tid & 1) * 64;
        const float* sp = &Dsm[rr * DP + cb];
        const size_t base = (size_t)(m0 + rr) * A_ + cb;
#pragma unroll
        for (int u = 0; u < 8; u++) {
            float f[8];
#pragma unroll
            for (int j = 0; j < 8; j++) f[j] = sp[8 * u + j] * sc;
            uint4 h = make_uint4(pack_bf16_hi(f[0], f[1]), pack_bf16_hi(f[2], f[3]),
                                 pack_bf16_hi(f[4], f[5]), pack_bf16_hi(f[6], f[7]));
            uint4 l = make_uint4(pack_bf16_lo(f[0], f[1]), pack_bf16_lo(f[2], f[3]),
                                 pack_bf16_lo(f[4], f[5]), pack_bf16_lo(f[6], f[7]));
            *(uint4*)(dsth + base + 8 * u) = h;
            *(uint4*)(dstl + base + 8 * u) = l;
        }
    }
}

// ---------------------------------------------------------------------------
// Split-K flash attention chunk kernel.
// Work unit = (b, qt [64 queries], chunk of <=8 key-tiles of 64). 320 CTAs.
// Block 256 = 8 warps: 4 row-groups (16 rows) x 2 key-halves (32 keys)
// -> 2 warps/SMSP so softmax/pack latency hides under partner's HMMA.
// Single-chunk qt (0..7) write out directly; others write (O,m,l) partials.
// ---------------------------------------------------------------------------
#define AQP 68                 // q/k tile pitch (words); 68%32==4 -> CF frags
#define AVP 36                 // v^T tile pitch
#define QW (64 * AQP)          // 4352 words
#define VW (128 * AVP)         // 4608 words
#define ATTN_SMEM ((4 * QW + 2 * VW) * 4)   // 106496 B

__global__ __launch_bounds__(256) void attn_chunk(float* __restrict__ out)
{
    extern __shared__ unsigned smw[];
    unsigned* qh = smw;
    unsigned* ql = qh + QW;
    unsigned* kh = ql + QW;
    unsigned* kl = kh + QW;
    unsigned* vh = kl + QW;
    unsigned* vl = vh + VW;
    float* obuf = (float*)kh;       // epilogue reuse: 64*128 f32 = 32KB < 2*QW*4
    __shared__ float red_m[2][4][16];
    __shared__ float red_s[2][4][16];

    int cid = blockIdx.x;           // 0..319
    const int b = cid / 80;  cid -= b * 80;
    int qt, chunk;
    if (cid < 8)       { qt = cid;                    chunk = 0; }
    else if (cid < 24) { qt = 8  + ((cid - 8) >> 1);  chunk = (cid - 8) & 1; }
    else if (cid < 48) { qt = 16 + (cid - 24) / 3;    chunk = (cid - 24) % 3; }
    else               { qt = 24 + ((cid - 48) >> 2); chunk = (cid - 48) & 3; }
    const int nch   = (qt >> 3) + 1;         // ceil((qt+1)/8)
    const int tbase = chunk * 8;
    int ntile = qt + 1 - tbase;
    if (ntile > 8) ntile = 8;
    const int q0 = qt * 64;

    const int tid  = threadIdx.x;
    const int wid  = tid >> 5;
    const int lane = tid & 31;
    const int wr   = wid >> 1;      // row group (16 rows)
    const int wh   = wid & 1;       // key half (32 keys)
    const int g    = lane >> 2;
    const int t    = lane & 3;

    // stage Q tile (64 rows x 128 d, hi/lo)
    {
        const int row = tid >> 2;
        const int qd  = (tid & 3) * 16;      // word offset
        const size_t e = (size_t)(b * S_ + q0 + row) * A_ + (tid & 3) * 32;
        const uint4* sh = (const uint4*)(g_qhi + e);
        const uint4* sl = (const uint4*)(g_qlo + e);
        const int wb = row * AQP + qd;
#pragma unroll
        for (int u = 0; u < 4; u++) {
            *(uint4*)&qh[wb + 4 * u] = sh[u];
            *(uint4*)&ql[wb + 4 * u] = sl[u];
        }
    }

    float o[16][4];
#pragma unroll
    for (int nt = 0; nt < 16; nt++)
#pragma unroll
        for (int q = 0; q < 4; q++) o[nt][q] = 0.f;
    float m0r = -1e30f, m1r = -1e30f, l0r = 0.f, l1r = 0.f;

    for (int tt = 0; tt < ntile; tt++) {
        const int kb = (tbase + tt) * 64;
        __syncthreads();   // Q ready (tt=0) / prev tile fully consumed
        {
            const int row = tid >> 2;
            const int qd  = (tid & 3) * 16;
            const size_t e = (size_t)(b * S_ + kb + row) * A_ + (tid & 3) * 32;
            const uint4* sh = (const uint4*)(g_khi + e);
            const uint4* sl = (const uint4*)(g_klo + e);
            const int wb = row * AQP + qd;
#pragma unroll
            for (int u = 0; u < 4; u++) {
                *(uint4*)&kh[wb + 4 * u] = sh[u];
                *(uint4*)&kl[wb + 4 * u] = sl[u];
            }
            const int vr = tid >> 1;
            const size_t ev = (size_t)(b * A_ + vr) * S_ + kb + (tid & 1) * 32;
            const uint4* vsh = (const uint4*)(g_vthi + ev);
            const uint4* vsl = (const uint4*)(g_vtlo + ev);
            const int vb = vr * AVP + (tid & 1) * 16;
#pragma unroll
            for (int u = 0; u < 4; u++) {
                *(uint4*)&vh[vb + 4 * u] = vsh[u];
                *(uint4*)&vl[vb + 4 * u] = vsl[u];
            }
        }
        __syncthreads();

        // ---- S = Q K^T over this warp's 16 rows x 32 keys (3-split) ----
        float s[4][4];
#pragma unroll
        for (int nt = 0; nt < 4; nt++)
#pragma unroll
            for (int q = 0; q < 4; q++) s[nt][q] = 0.f;

#pragma unroll
        for (int ks = 0; ks < 8; ks++) {
            const int r0 = (wr * 16 + g) * AQP + ks * 8 + t;
            const int r1 = r0 + 8 * AQP;
            unsigned ah[4]  = { qh[r0], qh[r1], qh[r0 + 4], qh[r1 + 4] };
            unsigned al_[4] = { ql[r0], ql[r1], ql[r0 + 4], ql[r1 + 4] };
#pragma unroll
            for (int nt = 0; nt < 4; nt++) {
                const int bw = (wh * 32 + nt * 8 + g) * AQP + ks * 8 + t;
                unsigned bh[2] = { kh[bw], kh[bw + 4] };
                unsigned bl[2] = { kl[bw], kl[bw + 4] };
                mma16816(s[nt], ah, bh);
                mma16816(s[nt], ah, bl);
                mma16816(s[nt], al_, bh);
            }
        }

        // causal mask: only the diagonal key-tile (global tile index == qt)
        if (tbase + tt == qt) {
            const int row0 = q0 + wr * 16 + g;
#pragma unroll
            for (int nt = 0; nt < 4; nt++) {
                const int c0 = kb + wh * 32 + nt * 8 + 2 * t;
                if (c0     > row0)     s[nt][0] = -1e30f;
                if (c0 + 1 > row0)     s[nt][1] = -1e30f;
                if (c0     > row0 + 8) s[nt][2] = -1e30f;
                if (c0 + 1 > row0 + 8) s[nt][3] = -1e30f;
            }
        }

        // ---- online softmax with cross-half combine ----
        float mx0 = -1e30f, mx1 = -1e30f;
#pragma unroll
        for (int nt = 0; nt < 4; nt++) {
            mx0 = fmaxf(mx0, fmaxf(s[nt][0], s[nt][1]));
            mx1 = fmaxf(mx1, fmaxf(s[nt][2], s[nt][3]));
        }
        mx0 = fmaxf(mx0, __shfl_xor_sync(0xffffffffu, mx0, 1));
        mx0 = fmaxf(mx0, __shfl_xor_sync(0xffffffffu, mx0, 2));
        mx1 = fmaxf(mx1, __shfl_xor_sync(0xffffffffu, mx1, 1));
        mx1 = fmaxf(mx1, __shfl_xor_sync(0xffffffffu, mx1, 2));
        if (t == 0) {
            red_m[wh][wr][g]     = mx0;
            red_m[wh][wr][g + 8] = mx1;
        }
        __syncthreads();
        const float mn0 = fmaxf(m0r, fmaxf(mx0, red_m[wh ^ 1][wr][g]));
        const float mn1 = fmaxf(m1r, fmaxf(mx1, red_m[wh ^ 1][wr][g + 8]));
        const float a0 = __expf(m0r - mn0), a1 = __expf(m1r - mn1);
        float sum0 = 0.f, sum1 = 0.f;
#pragma unroll
        for (int nt = 0; nt < 4; nt++) {
            s[nt][0] = __expf(s[nt][0] - mn0);
            s[nt][1] = __expf(s[nt][1] - mn0);
            s[nt][2] = __expf(s[nt][2] - mn1);
            s[nt][3] = __expf(s[nt][3] - mn1);
            sum0 += s[nt][0] + s[nt][1];
            sum1 += s[nt][2] + s[nt][3];
        }
        sum0 += __shfl_xor_sync(0xffffffffu, sum0, 1);
        sum0 += __shfl_xor_sync(0xffffffffu, sum0, 2);
        sum1 += __shfl_xor_sync(0xffffffffu, sum1, 1);
        sum1 += __shfl_xor_sync(0xffffffffu, sum1, 2);
        if (t == 0) {
            red_s[wh][wr][g]     = sum0;
            red_s[wh][wr][g + 8] = sum1;
        }
        // rescale O while red_s settles
#pragma unroll
        for (int nt = 0; nt < 16; nt++) {
            o[nt][0] *= a0; o[nt][1] *= a0;
            o[nt][2] *= a1; o[nt][3] *= a1;
        }
        __syncthreads();
        l0r = l0r * a0 + sum0 + red_s[wh ^ 1][wr][g];
        l1r = l1r * a1 + sum1 + red_s[wh ^ 1][wr][g + 8];
        m0r = mn0;  m1r = mn1;

        // ---- O += P V over this warp's 32 keys (P frags straight from S) ----
#pragma unroll
        for (int ks2 = 0; ks2 < 2; ks2++) {
            unsigned pa_h[4], pa_l[4];
            pa_h[0] = pack_bf16_hi(s[2*ks2  ][0], s[2*ks2  ][1]);
            pa_h[1] = pack_bf16_hi(s[2*ks2  ][2], s[2*ks2  ][3]);
            pa_h[2] = pack_bf16_hi(s[2*ks2+1][0], s[2*ks2+1][1]);
            pa_h[3] = pack_bf16_hi(s[2*ks2+1][2], s[2*ks2+1][3]);
            pa_l[0] = pack_bf16_lo(s[2*ks2  ][0], s[2*ks2  ][1]);
            pa_l[1] = pack_bf16_lo(s[2*ks2  ][2], s[2*ks2  ][3]);
            pa_l[2] = pack_bf16_lo(s[2*ks2+1][0], s[2*ks2+1][1]);
            pa_l[3] = pack_bf16_lo(s[2*ks2+1][2], s[2*ks2+1][3]);
#pragma unroll
            for (int nt2 = 0; nt2 < 16; nt2++) {
                const int bw = (nt2 * 8 + g) * AVP + wh * 16 + ks2 * 8 + t;
                unsigned bh[2] = { vh[bw], vh[bw + 4] };
                unsigned bl[2] = { vl[bw], vl[bw + 4] };
                mma16816(o[nt2], pa_h, bh);
                mma16816(o[nt2], pa_h, bl);
                mma16816(o[nt2], pa_l, bh);
            }
        }
    }

    // ---- pair-sum across key halves, then output ----
    __syncthreads();   // all warps done reading kh/kl (obuf aliases it)
    if (wh == 1) {
#pragma unroll
        for (int nt = 0; nt < 16; nt++) {
            const int r0 = wr * 16 + g;
            const int c  = nt * 8 + 2 * t;
            *(float2*)&obuf[r0 * 128 + c]       = make_float2(o[nt][0], o[nt][1]);
            *(float2*)&obuf[(r0 + 8) * 128 + c] = make_float2(o[nt][2], o[nt][3]);
        }
    }
    __syncthreads();
    if (wh == 0) {
#pragma unroll
        for (int nt = 0; nt < 16; nt++) {
            const int r0 = wr * 16 + g;
            const int c  = nt * 8 + 2 * t;
            float2 u0 = *(const float2*)&obuf[r0 * 128 + c];
            float2 u1 = *(const float2*)&obuf[(r0 + 8) * 128 + c];
            o[nt][0] += u0.x; o[nt][1] += u0.y;
            o[nt][2] += u1.x; o[nt][3] += u1.y;
        }
        if (nch == 1) {
            const float i0 = 1.f / l0r, i1 = 1.f / l1r;
            const size_t row0 = (size_t)(b * S_ + q0 + wr * 16 + g);
#pragma unroll
            for (int nt = 0; nt < 16; nt++) {
                const int c = nt * 8 + 2 * t;
                *(float2*)&out[row0 * A_ + c] =
                    make_float2(o[nt][0] * i0, o[nt][1] * i0);
                *(float2*)&out[(row0 + 8) * A_ + c] =
                    make_float2(o[nt][2] * i1, o[nt][3] * i1);
            }
        } else {
            const size_t pb = (size_t)(b * 32 + qt) * 4 + chunk;
            float* PO = g_po + pb * 8192;
            const int r0 = wr * 16 + g;
#pragma unroll
            for (int nt = 0; nt < 16; nt++) {
                const int c = nt * 8 + 2 * t;
                *(float2*)&PO[r0 * 128 + c]       = make_float2(o[nt][0], o[nt][1]);
                *(float2*)&PO[(r0 + 8) * 128 + c] = make_float2(o[nt][2], o[nt][3]);
            }
            if (t == 0) {
                g_pml[pb * 64 + r0]     = make_float2(m0r, l0r);
                g_pml[pb * 64 + r0 + 8] = make_float2(m1r, l1r);
            }
        }
    }
}

// ---------------------------------------------------------------------------
// Combine kernel: merge 2..4 chunk partials for qt >= 8.
// grid (24, 4), block 256; thread handles 1 row x 32 cols.
// ---------------------------------------------------------------------------
__global__ __launch_bounds__(256) void attn_combine(float* __restrict__ out)
{
    const int qt  = 8 + blockIdx.x;       // 8..31
    const int b   = blockIdx.y;
    const int nch = (qt >> 3) + 1;        // 2..4
    const int tid = threadIdx.x;
    const int row = tid >> 2;             // 0..63
    const int cq  = (tid & 3) * 32;

    const size_t pb0 = (size_t)(b * 32 + qt) * 4;
    float w[4], lv[4];
    float M = -1e30f;
    for (int c = 0; c < nch; c++) {
        float2 ml = g_pml[(pb0 + c) * 64 + row];
        w[c] = ml.x; lv[c] = ml.y;
        M = fmaxf(M, ml.x);
    }
    float L = 0.f;
    for (int c = 0; c < nch; c++) {
        w[c] = __expf(w[c] - M);
        L += w[c] * lv[c];
    }
    const float invL = 1.f / L;

    const size_t ob = (size_t)(b * S_ + qt * 64 + row) * A_ + cq;
#pragma unroll
    for (int j = 0; j < 32; j += 4) {
        float4 acc = make_float4(0.f, 0.f, 0.f, 0.f);
        for (int c = 0; c < nch; c++) {
            const float4 v = *(const float4*)
                &g_po[(pb0 + c) * 8192 + row * 128 + cq + j];
            acc.x += w[c] * v.x; acc.y += w[c] * v.y;
            acc.z += w[c] * v.z; acc.w += w[c] * v.w;
        }
        *(float4*)&out[ob + j] = make_float4(acc.x * invL, acc.y * invL,
                                             acc.z * invL, acc.w * invL);
    }
}

// ---------------------------------------------------------------------------
extern "C" void kernel_launch(void* const* d_in, const int* in_sizes, int n_in,
                              void* d_out, int out_size)
{
    const float* x  = (const float*)d_in[0];   // embedded [4,2048,1024]
    const float* Wk = (const float*)d_in[1];   // [128,1024]
    const float* Wq = (const float*)d_in[2];
    const float* Wv = (const float*)d_in[3];
    float* out = (float*)d_out;                // [4,2048,128] fp32

    cudaFuncSetAttribute(proj_mma2,
                         cudaFuncAttributeMaxDynamicSharedMemorySize,
                         PROJ_SMEM);
    cudaFuncSetAttribute(attn_chunk,
                         cudaFuncAttributeMaxDynamicSharedMemorySize,
                         ATTN_SMEM);

    split_xw<<<4096, 256>>>(x, Wk, Wq, Wv);
    proj_mma2<<<dim3(64, 3), 256, PROJ_SMEM>>>();
    attn_chunk<<<320, 256, ATTN_SMEM>>>(out);
    attn_combine<<<dim3(24, 4), 256>>>(out);
}